// round 9
// baseline (speedup 1.0000x reference)
#include <cuda_runtime.h>
#include <cuda_fp16.h>

#define N_NODES 50000
#define N_EDGES 800000
#define DIM     128
#define EPSN    1e-12f
#define XSCALE  8.0f        // per-iteration rescale; cancels exactly in the combine
#define NB      ((N_NODES + 255) / 256)

// ---------------- static device scratch (no allocations allowed) ----------------
__device__ float  g_deg[N_NODES];
__device__ int    g_cnt[N_NODES];
__device__ int    g_cur[N_NODES];
__device__ int    g_rowptr[N_NODES + 1];  // per-block partial prefixes; add g_boff
__device__ int    g_bsum[NB];
__device__ int    g_boff[NB];
__device__ int    g_col[N_EDGES];         // CSR cols only (edge_val == 1 exactly)
__device__ uint4  g_xa[N_NODES * 16];     // fp16 x: 8 halves per uint4, 16 per row
__device__ uint4  g_xb[N_NODES * 16];
__device__ uint4  g_xc[N_NODES * 16];
__device__ uint4  g_xd[N_NODES * 16];
__device__ float  g_sc0[N_NODES];
__device__ float  g_sc1[N_NODES];
__device__ float  g_sc2[N_NODES];
__device__ float  g_colsum[DIM];
__device__ float  g_colsq[DIM];

// ---------------- helpers ----------------
__device__ __forceinline__ void unpack8(uint4 p, float* f)
{
    float2 a = __half22float2(*(__half2*)&p.x);
    float2 b = __half22float2(*(__half2*)&p.y);
    float2 c = __half22float2(*(__half2*)&p.z);
    float2 d = __half22float2(*(__half2*)&p.w);
    f[0] = a.x; f[1] = a.y; f[2] = b.x; f[3] = b.y;
    f[4] = c.x; f[5] = c.y; f[6] = d.x; f[7] = d.y;
}

__device__ __forceinline__ uint4 pack8(const float* f)
{
    __half2 a = __floats2half2_rn(f[0], f[1]);
    __half2 b = __floats2half2_rn(f[2], f[3]);
    __half2 c = __floats2half2_rn(f[4], f[5]);
    __half2 d = __floats2half2_rn(f[6], f[7]);
    uint4 u;
    u.x = *(unsigned*)&a; u.y = *(unsigned*)&b;
    u.z = *(unsigned*)&c; u.w = *(unsigned*)&d;
    return u;
}

__device__ __forceinline__ int warp_incl_scan(int x, int lane)
{
    #pragma unroll
    for (int o = 1; o < 32; o <<= 1) {
        int y = __shfl_up_sync(0xffffffffu, x, o);
        if (lane >= o) x += y;
    }
    return x;
}

// Half-warp row gather-accumulate: 16 lanes, one uint4 per lane, unified
// predicated loop so both halves of the warp keep loads in flight together.
__device__ __forceinline__ void row_accum16(const uint4* __restrict__ xin,
                                            int s, int n, int nmax, int hl,
                                            float* a)
{
    const uint4 z = make_uint4(0u, 0u, 0u, 0u);
    for (int b = 0; b < nmax; b += 8) {
        int c[8];
        uint4 p[8];
        #pragma unroll
        for (int k = 0; k < 8; k++) c[k] = (b + k < n) ? g_col[s + b + k] : -1;
        #pragma unroll
        for (int k = 0; k < 8; k++) p[k] = (c[k] >= 0) ? xin[c[k] * 16 + hl] : z;
        #pragma unroll
        for (int k = 0; k < 8; k++) {
            float f[8];
            unpack8(p[k], f);
            #pragma unroll
            for (int j = 0; j < 8; j++) a[j] += f[j];
        }
    }
}

// ---------------- kernels ----------------

__global__ void k_init()
{
    int i = blockIdx.x * blockDim.x + threadIdx.x;
    if (i < N_NODES) {
        g_cnt[i] = 0;
        g_cur[i] = 0;
    }
    if (i < DIM) {
        g_colsum[i] = 0.0f;
        g_colsq[i]  = 0.0f;
    }
}

// Edge counts only — degree == count since edge_val is all-ones.
__global__ void k_hist(const int* __restrict__ erow)
{
    int e = blockIdx.x * blockDim.x + threadIdx.x;
    if (e < N_EDGES) atomicAdd(&g_cnt[erow[e]], 1);
}

// Phase A: per-block exclusive scan of counts; derive deg = max(cnt, 1).
__global__ __launch_bounds__(256) void k_scanA()
{
    __shared__ int wsum[32];
    int tid  = threadIdx.x;
    int lane = tid & 31, wid = tid >> 5;
    int i    = blockIdx.x * 256 + tid;
    int v    = (i < N_NODES) ? g_cnt[i] : 0;

    if (i < N_NODES) g_deg[i] = (v == 0) ? 1.0f : (float)v;

    int x = warp_incl_scan(v, lane);
    if (lane == 31) wsum[wid] = x;
    __syncthreads();
    if (wid == 0) {
        int s = (lane < 8) ? wsum[lane] : 0;
        s = warp_incl_scan(s, lane);
        if (lane < 8) wsum[lane] = s;
    }
    __syncthreads();
    int excl = x - v + (wid ? wsum[wid - 1] : 0);
    if (i < N_NODES) g_rowptr[i] = excl;
    if (tid == 0) g_bsum[blockIdx.x] = wsum[7];
}

// Phase B: scan block totals -> g_boff; pre-compensate rowptr[N_NODES].
__global__ __launch_bounds__(256) void k_scanB()
{
    __shared__ int wsum[32];
    int tid  = threadIdx.x;
    int lane = tid & 31, wid = tid >> 5;
    int v    = (tid < NB) ? g_bsum[tid] : 0;

    int x = warp_incl_scan(v, lane);
    if (lane == 31) wsum[wid] = x;
    __syncthreads();
    if (wid == 0) {
        int s = (lane < 8) ? wsum[lane] : 0;
        s = warp_incl_scan(s, lane);
        if (lane < 8) wsum[lane] = s;
    }
    __syncthreads();
    int myoff = x - v + (wid ? wsum[wid - 1] : 0);
    if (tid < NB) g_boff[tid] = myoff;
    if (tid == (N_NODES >> 8)) g_rowptr[N_NODES] = N_EDGES - myoff;
}

// Scatter cols into CSR order, then grid-stride init of x0 = R * deg^(-1/2).
__global__ void k_scatter(const int* __restrict__ erow, const int* __restrict__ ecol,
                          const float4* __restrict__ R)
{
    int e = blockIdx.x * blockDim.x + threadIdx.x;
    if (e < N_EDGES) {
        int r = erow[e];
        int p = g_rowptr[r] + g_boff[r >> 8] + atomicAdd(&g_cur[r], 1);
        g_col[p] = ecol[e];
    }
    int total = N_NODES * 16;
    for (int i = e; i < total; i += gridDim.x * blockDim.x) {
        int node = i >> 4;
        float s = rsqrtf(g_deg[node]);
        float4 r0 = R[i * 2];
        float4 r1 = R[i * 2 + 1];
        float f[8] = { r0.x * s, r0.y * s, r0.z * s, r0.w * s,
                       r1.x * s, r1.y * s, r1.z * s, r1.w * s };
        g_xa[i] = pack8(f);
    }
}

// SpMM iters 0..2: two rows per warp (16 lanes each). Gather, inv-deg, norm;
// store x_{i+1} (fp16, XSCALE) + combine scale.
__global__ __launch_bounds__(256) void k_spmm(const uint4* __restrict__ xin,
                                              uint4* __restrict__ xout,
                                              float* __restrict__ scarr, float w)
{
    int gtid = blockIdx.x * 256 + threadIdx.x;
    int lane = threadIdx.x & 31;
    int half = lane >> 4;
    int hl   = lane & 15;
    int row  = (gtid >> 5) * 2 + half;        // 3125 blocks exactly cover 50000 rows

    int s = g_rowptr[row]     + g_boff[row >> 8];
    int e = g_rowptr[row + 1] + g_boff[(row + 1) >> 8];
    int n = e - s;
    int nmax = max(n, __shfl_xor_sync(0xffffffffu, n, 16));

    float a[8] = {0.f, 0.f, 0.f, 0.f, 0.f, 0.f, 0.f, 0.f};
    row_accum16(xin, s, n, nmax, hl, a);

    float id = 1.0f / g_deg[row];
    float ss = 0.f;
    #pragma unroll
    for (int j = 0; j < 8; j++) { a[j] *= id; ss += a[j] * a[j]; }
    #pragma unroll
    for (int o = 8; o; o >>= 1) ss += __shfl_xor_sync(0xffffffffu, ss, o);

    float nrm = fmaxf(sqrtf(ss), EPSN);
    if (hl == 0) scarr[row] = w / (nrm * XSCALE);

    float sf[8];
    #pragma unroll
    for (int j = 0; j < 8; j++) sf[j] = a[j] * XSCALE;
    xout[row * 16 + hl] = pack8(sf);
}

// Last SpMM: iter-3 gather + combine all four weighted terms + column stats.
__global__ __launch_bounds__(256) void k_spmm_last(float4* __restrict__ out, float w)
{
    __shared__ float cs[DIM];
    __shared__ float cq[DIM];

    int tid  = threadIdx.x;
    int gtid = blockIdx.x * 256 + tid;
    int lane = tid & 31;
    int half = lane >> 4;
    int hl   = lane & 15;
    int row  = (gtid >> 5) * 2 + half;

    if (tid < DIM) { cs[tid] = 0.0f; cq[tid] = 0.0f; }
    __syncthreads();

    int s = g_rowptr[row]     + g_boff[row >> 8];
    int e = g_rowptr[row + 1] + g_boff[(row + 1) >> 8];
    int n = e - s;
    int nmax = max(n, __shfl_xor_sync(0xffffffffu, n, 16));

    float a[8] = {0.f, 0.f, 0.f, 0.f, 0.f, 0.f, 0.f, 0.f};
    row_accum16(g_xd, s, n, nmax, hl, a);

    float id = 1.0f / g_deg[row];
    float ss = 0.f;
    #pragma unroll
    for (int j = 0; j < 8; j++) { a[j] *= id; ss += a[j] * a[j]; }
    #pragma unroll
    for (int o = 8; o; o >>= 1) ss += __shfl_xor_sync(0xffffffffu, ss, o);

    float nrm = fmaxf(sqrtf(ss), EPSN);
    float sc3 = w / nrm;

    int base = row * 16 + hl;
    float s0 = g_sc0[row], s1 = g_sc1[row], s2 = g_sc2[row];

    float f1[8], f2[8], f3[8];
    unpack8(g_xb[base], f1);
    unpack8(g_xc[base], f2);
    unpack8(g_xd[base], f3);

    float o8[8];
    #pragma unroll
    for (int j = 0; j < 8; j++)
        o8[j] = s0 * f1[j] + s1 * f2[j] + s2 * f3[j] + sc3 * a[j];

    out[row * 32 + hl * 2]     = make_float4(o8[0], o8[1], o8[2], o8[3]);
    out[row * 32 + hl * 2 + 1] = make_float4(o8[4], o8[5], o8[6], o8[7]);

    int c0 = hl * 8;
    #pragma unroll
    for (int j = 0; j < 8; j++) {
        atomicAdd(&cs[c0 + j], o8[j]);
        atomicAdd(&cq[c0 + j], o8[j] * o8[j]);
    }
    __syncthreads();
    if (tid < DIM) {
        atomicAdd(&g_colsum[tid], cs[tid]);
        atomicAdd(&g_colsq[tid],  cq[tid]);
    }
}

__global__ void k_std(float* __restrict__ out)
{
    int i = blockIdx.x * blockDim.x + threadIdx.x;
    if (i < N_NODES * DIM) {
        int c = i & (DIM - 1);
        const float n = (float)N_NODES;
        float mean = g_colsum[c] / n;
        float var  = (g_colsq[c] - n * mean * mean) / (n - 1.0f);
        var = fmaxf(var, 0.0f);
        float sd = sqrtf(var);
        if (sd == 0.0f) sd = 1.0f;
        out[i] = (out[i] - mean) / sd;
    }
}

// ---------------- launcher ----------------

extern "C" void kernel_launch(void* const* d_in, const int* in_sizes, int n_in,
                              void* d_out, int out_size)
{
    const int*   erow = (const int*)d_in[0];
    const int*   ecol = (const int*)d_in[1];
    const float* R    = (const float*)d_in[3];
    float*       out  = (float*)d_out;

    const int spmm_blocks = (N_NODES / 2 * 32 + 255) / 256;   // 3125: 2 rows/warp

    uint4 *xa, *xb, *xc, *xd;
    float *sc0, *sc1, *sc2;
    cudaGetSymbolAddress((void**)&xa,  g_xa);
    cudaGetSymbolAddress((void**)&xb,  g_xb);
    cudaGetSymbolAddress((void**)&xc,  g_xc);
    cudaGetSymbolAddress((void**)&xd,  g_xd);
    cudaGetSymbolAddress((void**)&sc0, g_sc0);
    cudaGetSymbolAddress((void**)&sc1, g_sc1);
    cudaGetSymbolAddress((void**)&sc2, g_sc2);

    k_init<<<(N_NODES + 255) / 256, 256>>>();
    k_hist<<<(N_EDGES + 255) / 256, 256>>>(erow);
    k_scanA<<<NB, 256>>>();
    k_scanB<<<1, 256>>>();
    k_scatter<<<(N_EDGES + 255) / 256, 256>>>(erow, ecol, (const float4*)R);

    k_spmm<<<spmm_blocks, 256>>>(xa, xb, sc0, 1.0f);
    k_spmm<<<spmm_blocks, 256>>>(xb, xc, sc1, 1.0f);
    k_spmm<<<spmm_blocks, 256>>>(xc, xd, sc2, 7.81f);
    k_spmm_last<<<spmm_blocks, 256>>>((float4*)d_out, 45.28f);

    k_std<<<(N_NODES * DIM + 255) / 256, 256>>>(out);
}

// round 15
// speedup vs baseline: 1.1881x; 1.1881x over previous
#include <cuda_runtime.h>
#include <cuda_fp16.h>

#define N_NODES 50000
#define N_EDGES 800000
#define DIM     128
#define EPSN    1e-12f
#define XSCALE  8.0f        // per-iteration rescale; cancels exactly in the combine
#define NB      ((N_NODES + 255) / 256)

// ---------------- static device scratch (no allocations allowed) ----------------
__device__ float  g_deg[N_NODES];
__device__ int    g_cnt[N_NODES];
__device__ int    g_cur[N_NODES];
__device__ int    g_rowptr[N_NODES + 1];  // per-block partial prefixes; add g_boff
__device__ int    g_bsum[NB];
__device__ int    g_boff[NB];
__device__ int    g_col[N_EDGES];         // CSR cols only (edge_val == 1 exactly)
__device__ uint2  g_xa[N_NODES * 32];     // fp16 x: 4 halves per uint2, 32 per row
__device__ uint2  g_xb[N_NODES * 32];
__device__ uint2  g_xc[N_NODES * 32];
__device__ uint2  g_xd[N_NODES * 32];
__device__ float  g_sc0[N_NODES];
__device__ float  g_sc1[N_NODES];
__device__ float  g_sc2[N_NODES];
__device__ float  g_colsum[DIM];
__device__ float  g_colsq[DIM];

// ---------------- helpers ----------------
__device__ __forceinline__ void unpack4(uint2 p, float& a, float& b, float& c, float& d)
{
    float2 f0 = __half22float2(*(__half2*)&p.x);
    float2 f1 = __half22float2(*(__half2*)&p.y);
    a = f0.x; b = f0.y; c = f1.x; d = f1.y;
}

__device__ __forceinline__ uint2 pack4(float a, float b, float c, float d)
{
    __half2 h0 = __floats2half2_rn(a, b);
    __half2 h1 = __floats2half2_rn(c, d);
    uint2 u;
    u.x = *(unsigned*)&h0;
    u.y = *(unsigned*)&h1;
    return u;
}

__device__ __forceinline__ int warp_incl_scan(int x, int lane)
{
    #pragma unroll
    for (int o = 1; o < 32; o <<= 1) {
        int y = __shfl_up_sync(0xffffffffu, x, o);
        if (lane >= o) x += y;
    }
    return x;
}

// Warp-per-row gather-accumulate. edge_val == 1 -> pure adds, no multiply.
__device__ __forceinline__ void row_accum(const uint2* __restrict__ xin,
                                          int s, int e, int lane,
                                          float& ax, float& ay, float& az, float& aw)
{
    int j = s;
    for (; j + 8 <= e; j += 8) {
        int c[8];
        uint2 p[8];
        #pragma unroll
        for (int k = 0; k < 8; k++) c[k] = g_col[j + k];
        #pragma unroll
        for (int k = 0; k < 8; k++) p[k] = xin[c[k] * 32 + lane];
        #pragma unroll
        for (int k = 0; k < 8; k++) {
            float x0, y0, z0, w0;
            unpack4(p[k], x0, y0, z0, w0);
            ax += x0; ay += y0; az += z0; aw += w0;
        }
    }
    if (j + 4 <= e) {
        int c[4];
        uint2 p[4];
        #pragma unroll
        for (int k = 0; k < 4; k++) c[k] = g_col[j + k];
        #pragma unroll
        for (int k = 0; k < 4; k++) p[k] = xin[c[k] * 32 + lane];
        #pragma unroll
        for (int k = 0; k < 4; k++) {
            float x0, y0, z0, w0;
            unpack4(p[k], x0, y0, z0, w0);
            ax += x0; ay += y0; az += z0; aw += w0;
        }
        j += 4;
    }
    for (; j < e; j++) {
        uint2 p = xin[g_col[j] * 32 + lane];
        float x0, y0, z0, w0;
        unpack4(p, x0, y0, z0, w0);
        ax += x0; ay += y0; az += z0; aw += w0;
    }
}

// ---------------- kernels ----------------

__global__ void k_init()
{
    int i = blockIdx.x * blockDim.x + threadIdx.x;
    if (i < N_NODES) {
        g_cnt[i] = 0;
        g_cur[i] = 0;
    }
    if (i < DIM) {
        g_colsum[i] = 0.0f;
        g_colsq[i]  = 0.0f;
    }
}

// Edge counts only — degree == count since edge_val is all-ones.
__global__ void k_hist(const int* __restrict__ erow)
{
    int e = blockIdx.x * blockDim.x + threadIdx.x;
    if (e < N_EDGES) atomicAdd(&g_cnt[erow[e]], 1);
}

// Phase A: per-block exclusive scan of counts; derive deg = max(cnt, 1).
__global__ __launch_bounds__(256) void k_scanA()
{
    __shared__ int wsum[32];
    int tid  = threadIdx.x;
    int lane = tid & 31, wid = tid >> 5;
    int i    = blockIdx.x * 256 + tid;
    int v    = (i < N_NODES) ? g_cnt[i] : 0;

    if (i < N_NODES) g_deg[i] = (v == 0) ? 1.0f : (float)v;

    int x = warp_incl_scan(v, lane);
    if (lane == 31) wsum[wid] = x;
    __syncthreads();
    if (wid == 0) {
        int s = (lane < 8) ? wsum[lane] : 0;
        s = warp_incl_scan(s, lane);
        if (lane < 8) wsum[lane] = s;
    }
    __syncthreads();
    int excl = x - v + (wid ? wsum[wid - 1] : 0);
    if (i < N_NODES) g_rowptr[i] = excl;
    if (tid == 0) g_bsum[blockIdx.x] = wsum[7];
}

// Phase B: scan block totals -> g_boff; pre-compensate rowptr[N_NODES].
__global__ __launch_bounds__(256) void k_scanB()
{
    __shared__ int wsum[32];
    int tid  = threadIdx.x;
    int lane = tid & 31, wid = tid >> 5;
    int v    = (tid < NB) ? g_bsum[tid] : 0;

    int x = warp_incl_scan(v, lane);
    if (lane == 31) wsum[wid] = x;
    __syncthreads();
    if (wid == 0) {
        int s = (lane < 8) ? wsum[lane] : 0;
        s = warp_incl_scan(s, lane);
        if (lane < 8) wsum[lane] = s;
    }
    __syncthreads();
    int myoff = x - v + (wid ? wsum[wid - 1] : 0);
    if (tid < NB) g_boff[tid] = myoff;
    if (tid == (N_NODES >> 8)) g_rowptr[N_NODES] = N_EDGES - myoff;
}

// Scatter cols into CSR order, then grid-stride init of x0 = R * deg^(-1/2).
__global__ void k_scatter(const int* __restrict__ erow, const int* __restrict__ ecol,
                          const float4* __restrict__ R)
{
    int e = blockIdx.x * blockDim.x + threadIdx.x;
    if (e < N_EDGES) {
        int r = erow[e];
        int p = g_rowptr[r] + g_boff[r >> 8] + atomicAdd(&g_cur[r], 1);
        g_col[p] = ecol[e];
    }
    int total = N_NODES * 32;
    for (int i = e; i < total; i += gridDim.x * blockDim.x) {
        int node = i >> 5;
        float s = rsqrtf(g_deg[node]);
        float4 r = R[i];
        g_xa[i] = pack4(r.x * s, r.y * s, r.z * s, r.w * s);
    }
}

// SpMM iters 0..2: gather, inv-deg, norm; store x_{i+1} (fp16, XSCALE) + scale.
__global__ __launch_bounds__(256) void k_spmm(const uint2* __restrict__ xin,
                                              uint2* __restrict__ xout,
                                              float* __restrict__ scarr, float w)
{
    int gtid = blockIdx.x * blockDim.x + threadIdx.x;
    int row  = gtid >> 5;
    int lane = threadIdx.x & 31;
    if (row >= N_NODES) return;

    int s = g_rowptr[row]     + g_boff[row >> 8];
    int e = g_rowptr[row + 1] + g_boff[(row + 1) >> 8];

    float ax = 0.f, ay = 0.f, az = 0.f, aw = 0.f;
    row_accum(xin, s, e, lane, ax, ay, az, aw);

    float id = 1.0f / g_deg[row];
    ax *= id; ay *= id; az *= id; aw *= id;

    float ss = ax * ax + ay * ay + az * az + aw * aw;
    #pragma unroll
    for (int o = 16; o; o >>= 1) ss += __shfl_xor_sync(0xffffffffu, ss, o);

    float nrm = fmaxf(sqrtf(ss), EPSN);
    if (lane == 0) scarr[row] = w / (nrm * XSCALE);

    xout[row * 32 + lane] = pack4(ax * XSCALE, ay * XSCALE, az * XSCALE, aw * XSCALE);
}

// Last SpMM: iter-3 gather + combine all four weighted terms + column stats.
__global__ __launch_bounds__(256) void k_spmm_last(float4* __restrict__ out, float w)
{
    __shared__ float cs[DIM];
    __shared__ float cq[DIM];

    int tid  = threadIdx.x;
    int gtid = blockIdx.x * blockDim.x + tid;
    int row  = gtid >> 5;
    int lane = tid & 31;

    if (tid < DIM) { cs[tid] = 0.0f; cq[tid] = 0.0f; }
    __syncthreads();

    if (row < N_NODES) {
        int s = g_rowptr[row]     + g_boff[row >> 8];
        int e = g_rowptr[row + 1] + g_boff[(row + 1) >> 8];

        float ax = 0.f, ay = 0.f, az = 0.f, aw = 0.f;
        row_accum(g_xd, s, e, lane, ax, ay, az, aw);

        float id = 1.0f / g_deg[row];
        ax *= id; ay *= id; az *= id; aw *= id;

        float ss = ax * ax + ay * ay + az * az + aw * aw;
        #pragma unroll
        for (int o = 16; o; o >>= 1) ss += __shfl_xor_sync(0xffffffffu, ss, o);

        float nrm = fmaxf(sqrtf(ss), EPSN);
        float sc3 = w / nrm;

        int base = row * 32 + lane;
        float s0 = g_sc0[row], s1 = g_sc1[row], s2 = g_sc2[row];

        float x1, y1, z1, w1, x2, y2, z2, w2, x3, y3, z3, w3;
        unpack4(g_xb[base], x1, y1, z1, w1);
        unpack4(g_xc[base], x2, y2, z2, w2);
        unpack4(g_xd[base], x3, y3, z3, w3);

        float ox = s0 * x1 + s1 * x2 + s2 * x3 + sc3 * ax;
        float oy = s0 * y1 + s1 * y2 + s2 * y3 + sc3 * ay;
        float oz = s0 * z1 + s1 * z2 + s2 * z3 + sc3 * az;
        float ow = s0 * w1 + s1 * w2 + s2 * w3 + sc3 * aw;

        out[base] = make_float4(ox, oy, oz, ow);

        int c = 4 * lane;
        atomicAdd(&cs[c],     ox); atomicAdd(&cq[c],     ox * ox);
        atomicAdd(&cs[c + 1], oy); atomicAdd(&cq[c + 1], oy * oy);
        atomicAdd(&cs[c + 2], oz); atomicAdd(&cq[c + 2], oz * oz);
        atomicAdd(&cs[c + 3], ow); atomicAdd(&cq[c + 3], ow * ow);
    }
    __syncthreads();
    if (tid < DIM) {
        atomicAdd(&g_colsum[tid], cs[tid]);
        atomicAdd(&g_colsq[tid],  cq[tid]);
    }
}

__global__ void k_std(float* __restrict__ out)
{
    int i = blockIdx.x * blockDim.x + threadIdx.x;
    if (i < N_NODES * DIM) {
        int c = i & (DIM - 1);
        const float n = (float)N_NODES;
        float mean = g_colsum[c] / n;
        float var  = (g_colsq[c] - n * mean * mean) / (n - 1.0f);
        var = fmaxf(var, 0.0f);
        float sd = sqrtf(var);
        if (sd == 0.0f) sd = 1.0f;
        out[i] = (out[i] - mean) / sd;
    }
}

// ---------------- launcher ----------------

extern "C" void kernel_launch(void* const* d_in, const int* in_sizes, int n_in,
                              void* d_out, int out_size)
{
    const int*   erow = (const int*)d_in[0];
    const int*   ecol = (const int*)d_in[1];
    const float* R    = (const float*)d_in[3];
    float*       out  = (float*)d_out;

    const int warp_blocks = (N_NODES * 32 + 255) / 256;   // 6250: warp per row

    uint2 *xa, *xb, *xc, *xd;
    float *sc0, *sc1, *sc2;
    cudaGetSymbolAddress((void**)&xa,  g_xa);
    cudaGetSymbolAddress((void**)&xb,  g_xb);
    cudaGetSymbolAddress((void**)&xc,  g_xc);
    cudaGetSymbolAddress((void**)&xd,  g_xd);
    cudaGetSymbolAddress((void**)&sc0, g_sc0);
    cudaGetSymbolAddress((void**)&sc1, g_sc1);
    cudaGetSymbolAddress((void**)&sc2, g_sc2);

    k_init<<<(N_NODES + 255) / 256, 256>>>();
    k_hist<<<(N_EDGES + 255) / 256, 256>>>(erow);
    k_scanA<<<NB, 256>>>();
    k_scanB<<<1, 256>>>();
    k_scatter<<<(N_EDGES + 255) / 256, 256>>>(erow, ecol, (const float4*)R);

    k_spmm<<<warp_blocks, 256>>>(xa, xb, sc0, 1.0f);
    k_spmm<<<warp_blocks, 256>>>(xb, xc, sc1, 1.0f);
    k_spmm<<<warp_blocks, 256>>>(xc, xd, sc2, 7.81f);
    k_spmm_last<<<warp_blocks, 256>>>((float4*)d_out, 45.28f);

    k_std<<<(N_NODES * DIM + 255) / 256, 256>>>(out);
}